// round 10
// baseline (speedup 1.0000x reference)
#include <cuda_runtime.h>

// PCEN: s[t] = (1-c)*x[t] + c*s[t-1];  y = (x*(eps+s)^-alpha + delta)^root - delta^root
// x: [B=64, T=2048, F=128] fp32. Chunked-in-T (CT=16), float4 across F.
// 6-step warm-up (valid when c^6 <= 2^-21, runtime-checked; exact fallback).
// Main 16 steps fully unrolled as two depth-8 load groups (immediate offsets,
// no loop machinery). Streaming float4 stores.

#define B_DIM   64
#define T_DIM   2048
#define F_DIM   128
#define F4      (F_DIM / 4)       // 32 float4 per timestep row
#define CT      16                // timesteps per chunk
#define NCHUNK  (T_DIM / CT)      // 128
#define JPB     4                 // jobs per 128-thread block
#define WFIX    6                 // fixed warm-up steps on the fast path
#define EPS_F   1e-6f

__device__ __forceinline__ float lg2_approx(float x) {
    float r; asm("lg2.approx.f32 %0, %1;" : "=f"(r) : "f"(x)); return r;
}
__device__ __forceinline__ float ex2_approx(float x) {
    float r; asm("ex2.approx.f32 %0, %1;" : "=f"(r) : "f"(x)); return r;
}
__device__ __forceinline__ float sqrt_approx(float x) {
    float r; asm("sqrt.approx.f32 %0, %1;" : "=f"(r) : "f"(x)); return r;
}
__device__ __forceinline__ void stg_cs_f4(float4* p, float4 v) {
    asm volatile("st.global.cs.v4.f32 [%0], {%1, %2, %3, %4};"
                 :: "l"(p), "f"(v.x), "f"(v.y), "f"(v.z), "f"(v.w) : "memory");
}

struct PcenP { float c, omc, nalpha, delta, root, droot; bool half_root; };

__device__ __forceinline__ float pcen_one(float xv, float s, const PcenP& p) {
    const float m = EPS_F + s;
    const float r = ex2_approx(p.nalpha * lg2_approx(m));   // (eps+s)^-alpha
    const float u = fmaf(xv, r, p.delta);
    const float o = p.half_root ? sqrt_approx(u)
                                : ex2_approx(p.root * lg2_approx(u));
    return o - p.droot;
}

__global__ __launch_bounds__(128, 8)
void pcen_kernel(const float4* __restrict__ x,
                 const float* __restrict__ alpha_p,
                 const float* __restrict__ delta_p,
                 const float* __restrict__ root_p,
                 const float* __restrict__ c_p,
                 float4* __restrict__ y)
{
    const int job   = blockIdx.x * JPB + threadIdx.y;   // 0..8191
    const int b     = job >> 7;                         // /NCHUNK
    const int chunk = job & (NCHUNK - 1);
    const int t0    = chunk * CT;
    const int f4    = threadIdx.x;                      // 0..31 coalesced

    PcenP p;
    p.c      = __ldg(c_p);
    p.omc    = 1.0f - p.c;
    p.nalpha = -__ldg(alpha_p);
    p.delta  = __ldg(delta_p);
    p.root   = __ldg(root_p);
    p.half_root = (p.root == 0.5f);
    p.droot  = p.half_root ? sqrt_approx(p.delta)
                           : ex2_approx(p.root * lg2_approx(p.delta));
    const float c = p.c, omc = p.omc;

    const float4* __restrict__ px = x + (size_t)(b * T_DIM + t0) * F4 + f4;
    float4*       __restrict__ py = y + (size_t)(b * T_DIM + t0) * F4 + f4;

    float sx = 0.f, sy = 0.f, sz = 0.f, sw = 0.f;

    // ---- Warm-up: bring EMA state to t0 (state truncation ~c^WFIX) ----
    const float l2c  = (c > 0.0f) ? lg2_approx(c) : -128.0f;
    const bool  fast = (c <= 0.0f) || (l2c * (float)WFIX <= -21.0f); // c^6 <= 2^-21

    if (fast) {
        if (t0 > 0) {
            const float4* pw = px - WFIX * F4;
            float4 w[WFIX];
            #pragma unroll
            for (int t = 0; t < WFIX; ++t) w[t] = __ldg(pw + t * F4);  // batched
            #pragma unroll
            for (int t = 0; t < WFIX; ++t) {
                sx = fmaf(c, sx, omc * w[t].x);
                sy = fmaf(c, sy, omc * w[t].y);
                sz = fmaf(c, sz, omc * w[t].z);
                sw = fmaf(c, sw, omc * w[t].w);
            }
        }
    } else {
        int W = t0;                                      // exact scan from t=0
        if (l2c < -1e-6f) {
            float w = -21.0f / l2c;
            if (w < (float)t0) W = (int)w + 1;
        }
        const float4* pw = px - (size_t)W * F4;
        for (int t = 0; t < W; ++t) {
            const float4 xv = __ldg(pw); pw += F4;
            sx = fmaf(c, sx, omc * xv.x);
            sy = fmaf(c, sy, omc * xv.y);
            sz = fmaf(c, sz, omc * xv.z);
            sw = fmaf(c, sw, omc * xv.w);
        }
    }

    // ---- Main chunk: 16 steps, fully unrolled as two depth-8 groups ----
    #pragma unroll
    for (int g = 0; g < 2; ++g) {
        const int gb = g * 8;
        float4 xv[8];
        #pragma unroll
        for (int t = 0; t < 8; ++t) xv[t] = __ldg(px + (gb + t) * F4);  // 8 in flight

        #pragma unroll
        for (int t = 0; t < 8; ++t) {
            sx = fmaf(c, sx, omc * xv[t].x);
            sy = fmaf(c, sy, omc * xv[t].y);
            sz = fmaf(c, sz, omc * xv[t].z);
            sw = fmaf(c, sw, omc * xv[t].w);
            float4 o;
            o.x = pcen_one(xv[t].x, sx, p);
            o.y = pcen_one(xv[t].y, sy, p);
            o.z = pcen_one(xv[t].z, sz, p);
            o.w = pcen_one(xv[t].w, sw, p);
            stg_cs_f4(py + (gb + t) * F4, o);           // immediate offsets
        }
    }
}

extern "C" void kernel_launch(void* const* d_in, const int* in_sizes, int n_in,
                              void* d_out, int out_size)
{
    const float4* x      = (const float4*)d_in[0];
    const float* alpha_p = (const float*)d_in[1];
    const float* delta_p = (const float*)d_in[2];
    const float* root_p  = (const float*)d_in[3];
    const float* coef_p  = (const float*)d_in[4];
    float4* y = (float4*)d_out;

    const int jobs   = B_DIM * NCHUNK;          // 8192
    const int blocks = jobs / JPB;              // 2048
    dim3 block(F4, JPB, 1);                     // (32, 4) = 128 threads
    pcen_kernel<<<blocks, block>>>(x, alpha_p, delta_p, root_p, coef_p, y);
}

// round 11
// speedup vs baseline: 1.0717x; 1.0717x over previous
#include <cuda_runtime.h>

// PCEN: s[t] = (1-c)*x[t] + c*s[t-1];  y = (x*(eps+s)^-alpha + delta)^root - delta^root
// x: [B=64, T=2048, F=128] fp32. Chunked-in-T (CT=32), float4 across F (32 lanes/row).
// 8-step warm-up (valid when c^8 <= 2^-30, runtime-checked; exact fallback).
// Depth-8 load batching for MLP. Plain write-back stores (L2-resident output;
// dirty writeback overlaps compute instead of draining in-window like .cs did).

#define B_DIM   64
#define T_DIM   2048
#define F_DIM   128
#define F4      (F_DIM / 4)       // 32 float4 per timestep row
#define CT      32                // timesteps per chunk
#define NCHUNK  (T_DIM / CT)      // 64
#define JPB     4                 // jobs per 128-thread block
#define WFIX    8                 // fixed warm-up steps on the fast path
#define EPS_F   1e-6f

__device__ __forceinline__ float lg2_approx(float x) {
    float r; asm("lg2.approx.f32 %0, %1;" : "=f"(r) : "f"(x)); return r;
}
__device__ __forceinline__ float ex2_approx(float x) {
    float r; asm("ex2.approx.f32 %0, %1;" : "=f"(r) : "f"(x)); return r;
}
__device__ __forceinline__ float sqrt_approx(float x) {
    float r; asm("sqrt.approx.f32 %0, %1;" : "=f"(r) : "f"(x)); return r;
}

struct PcenP { float c, omc, nalpha, delta, root, droot; bool half_root; };

__device__ __forceinline__ float pcen_one(float xv, float s, const PcenP& p) {
    const float m = EPS_F + s;
    const float r = ex2_approx(p.nalpha * lg2_approx(m));   // (eps+s)^-alpha
    const float u = fmaf(xv, r, p.delta);
    const float o = p.half_root ? sqrt_approx(u)
                                : ex2_approx(p.root * lg2_approx(u));
    return o - p.droot;
}

__global__ __launch_bounds__(128, 8)
void pcen_kernel(const float4* __restrict__ x,
                 const float* __restrict__ alpha_p,
                 const float* __restrict__ delta_p,
                 const float* __restrict__ root_p,
                 const float* __restrict__ c_p,
                 float4* __restrict__ y)
{
    const int job   = blockIdx.x * JPB + threadIdx.y;   // 0..4095
    const int b     = job >> 6;                         // /NCHUNK
    const int chunk = job & (NCHUNK - 1);
    const int t0    = chunk * CT;
    const int f4    = threadIdx.x;                      // 0..31 coalesced

    PcenP p;
    p.c      = __ldg(c_p);
    p.omc    = 1.0f - p.c;
    p.nalpha = -__ldg(alpha_p);
    p.delta  = __ldg(delta_p);
    p.root   = __ldg(root_p);
    p.half_root = (p.root == 0.5f);
    p.droot  = p.half_root ? sqrt_approx(p.delta)
                           : ex2_approx(p.root * lg2_approx(p.delta));
    const float c = p.c, omc = p.omc;

    const float4* __restrict__ px = x + (size_t)(b * T_DIM + t0) * F4 + f4;
    float4*       __restrict__ py = y + (size_t)(b * T_DIM + t0) * F4 + f4;

    float sx = 0.f, sy = 0.f, sz = 0.f, sw = 0.f;

    // ---- Warm-up: bring EMA state to t0 (state truncation ~c^WFIX) ----
    const float l2c  = (c > 0.0f) ? lg2_approx(c) : -128.0f;
    const bool  fast = (c <= 0.0f) || (l2c * (float)WFIX <= -30.0f); // c^8 <= 2^-30

    if (fast) {
        if (t0 > 0) {
            const float4* pw = px - WFIX * F4;
            float4 w[WFIX];
            #pragma unroll
            for (int t = 0; t < WFIX; ++t) w[t] = __ldg(pw + t * F4);  // batched
            #pragma unroll
            for (int t = 0; t < WFIX; ++t) {
                sx = fmaf(c, sx, omc * w[t].x);
                sy = fmaf(c, sy, omc * w[t].y);
                sz = fmaf(c, sz, omc * w[t].z);
                sw = fmaf(c, sw, omc * w[t].w);
            }
        }
    } else {
        int W = t0;                                      // exact scan from t=0
        if (l2c < -1e-6f) {
            float w = -30.0f / l2c;
            if (w < (float)t0) W = (int)w + 1;
        }
        const float4* pw = px - (size_t)W * F4;
        for (int t = 0; t < W; ++t) {
            const float4 xv = __ldg(pw); pw += F4;
            sx = fmaf(c, sx, omc * xv.x);
            sy = fmaf(c, sy, omc * xv.y);
            sz = fmaf(c, sz, omc * xv.z);
            sw = fmaf(c, sw, omc * xv.w);
        }
    }

    // ---- Main chunk: 8 timesteps per iteration; all 8 loads in flight ----
    #pragma unroll 1
    for (int i = 0; i < CT; i += 8) {
        float4 xv[8];
        #pragma unroll
        for (int t = 0; t < 8; ++t) xv[t] = __ldg(px + t * F4);
        px += 8 * F4;

        #pragma unroll
        for (int t = 0; t < 8; ++t) {
            sx = fmaf(c, sx, omc * xv[t].x);
            sy = fmaf(c, sy, omc * xv[t].y);
            sz = fmaf(c, sz, omc * xv[t].z);
            sw = fmaf(c, sw, omc * xv[t].w);
            float4 o;
            o.x = pcen_one(xv[t].x, sx, p);
            o.y = pcen_one(xv[t].y, sy, p);
            o.z = pcen_one(xv[t].z, sz, p);
            o.w = pcen_one(xv[t].w, sw, p);
            py[t * F4] = o;                             // plain write-back store
        }
        py += 8 * F4;
    }
}

extern "C" void kernel_launch(void* const* d_in, const int* in_sizes, int n_in,
                              void* d_out, int out_size)
{
    const float4* x      = (const float4*)d_in[0];
    const float* alpha_p = (const float*)d_in[1];
    const float* delta_p = (const float*)d_in[2];
    const float* root_p  = (const float*)d_in[3];
    const float* coef_p  = (const float*)d_in[4];
    float4* y = (float4*)d_out;

    const int jobs   = B_DIM * NCHUNK;          // 4096
    const int blocks = jobs / JPB;              // 1024
    dim3 block(F4, JPB, 1);                     // (32, 4) = 128 threads
    pcen_kernel<<<blocks, block>>>(x, alpha_p, delta_p, root_p, coef_p, y);
}